// round 12
// baseline (speedup 1.0000x reference)
#include <cuda_runtime.h>
#include <cuda_fp16.h>
#include <cstdint>

constexpr int NN = 100000;   // nodes
constexpr int NE = 1600000;  // edges
constexpr int D  = 128;
// H=8, DH=16, scale=0.25

// ---------------- scratch ----------------------------------------------------
__device__ float  g_Q  [NN * D];        // Q rows fp32 (streamed in agg)
__device__ __half g_KVh[NN * 2 * D];    // per node: [K(128) | V(128)] fp16 (gathered)
__device__ float  g_Wpk[D * 3 * D];     // packed weights [k][Wq|Wk|Wv]
__device__ float  g_wV [NN * D];        // head_out
__device__ float  g_hh [NN * D];
__device__ float  g_t  [NN * 2 * D];    // FFN intermediate, fp32
__device__ int    g_cnt[NN];
__device__ int    g_off[NN + 1];
__device__ int    g_cur[NN];
__device__ int    g_bin[NE];            // src ids binned by dst

// ---------------- helpers -----------------------------------------------------
__device__ __forceinline__ float tf32f(float x) {
    uint32_t r;
    asm("cvt.rna.tf32.f32 %0, %1;" : "=r"(r) : "f"(x));
    return __uint_as_float(r);
}

__device__ __forceinline__ void mma_tf32(float* d, const uint32_t* a, const uint32_t* b) {
    asm volatile(
        "mma.sync.aligned.m16n8k8.row.col.f32.tf32.tf32.f32 "
        "{%0,%1,%2,%3}, {%4,%5,%6,%7}, {%8,%9}, {%0,%1,%2,%3};"
        : "+f"(d[0]), "+f"(d[1]), "+f"(d[2]), "+f"(d[3])
        : "r"(a[0]), "r"(a[1]), "r"(a[2]), "r"(a[3]), "r"(b[0]), "r"(b[1]));
}

// permute k within its 8-group so fragment pairs (k, k+4) become adjacent
__device__ __forceinline__ int kperm(int kl) {
    return ((kl >> 3) << 3) + ((kl & 3) << 1) + ((kl & 7) >> 2);
}

// ---------------- pack Wq|Wk|Wv into [128 x 384] -----------------------------
__global__ void __launch_bounds__(256)
packW_kernel(const float* __restrict__ Wq,
             const float* __restrict__ Wk,
             const float* __restrict__ Wv,
             float* __restrict__ P) {
    int i = blockIdx.x * blockDim.x + threadIdx.x;
    if (i >= D * D) return;
    int k = i / D, c = i % D;
    P[(size_t)k * (3 * D) + c]         = Wq[i];
    P[(size_t)k * (3 * D) + D + c]     = Wk[i];
    P[(size_t)k * (3 * D) + 2 * D + c] = Wv[i];
}

// ================= tf32 tensor-core GEMM, BM=BN=128, BK=16 ===================
// MODE 0: QKV split store (out=Q fp32 stride 128; outh=KV fp16 stride 256)
// MODE 1: out = relu(A@B + bias), fp32, generic N (grid.x = N/128)
// MODE 2: out = LN(res + A@B + bias)*lng + lnb, N==128, grid.x==1
template <int MODE>
__global__ void __launch_bounds__(256, 2)
mma_gemm(const float* __restrict__ A, const float* __restrict__ B,
         const float* __restrict__ bias, const float* __restrict__ res,
         const float* __restrict__ lng, const float* __restrict__ lnb,
         float* __restrict__ out, __half* __restrict__ outh,
         int M, int N, int K) {
    constexpr int S = 26;                 // smem row stride (floats, EVEN -> LDS.64 aligned)
    __shared__ __align__(16) float sm[2 * 128 * S];
    float* As = sm;
    float* Bs = sm + 128 * S;

    const int tid  = threadIdx.x;
    const int warp = tid >> 5;
    const int lane = tid & 31;
    const int g    = lane >> 2;
    const int tg   = lane & 3;
    const int wm   = warp & 3;
    const int wn   = warp >> 2;
    const int row0 = blockIdx.y * 128;
    const int col0 = blockIdx.x * 128;

    float acc[2][8][4];
#pragma unroll
    for (int i = 0; i < 2; i++)
#pragma unroll
        for (int j = 0; j < 8; j++)
#pragma unroll
            for (int q = 0; q < 4; q++) acc[i][j][q] = 0.f;

    for (int k0 = 0; k0 < K; k0 += 16) {
        // ---- A tile: 128 x 16, tf32-convert + permuted store ----
#pragma unroll
        for (int l = 0; l < 2; l++) {
            int fidx = tid + 256 * l;
            int r  = fidx >> 2;
            int kc = (fidx & 3) * 4;
            float4 v = make_float4(0.f, 0.f, 0.f, 0.f);
            if (row0 + r < M)
                v = *reinterpret_cast<const float4*>(&A[(size_t)(row0 + r) * K + k0 + kc]);
            As[r * S + kperm(kc + 0)] = tf32f(v.x);
            As[r * S + kperm(kc + 1)] = tf32f(v.y);
            As[r * S + kperm(kc + 2)] = tf32f(v.z);
            As[r * S + kperm(kc + 3)] = tf32f(v.w);
        }
        // ---- B tile: 16 x 128, transposed into Bs[n][k'] ----
#pragma unroll
        for (int l = 0; l < 2; l++) {
            int fidx = tid + 256 * l;
            int kr = fidx >> 5;
            int nc = (fidx & 31) * 4;
            float4 v = *reinterpret_cast<const float4*>(&B[(size_t)(k0 + kr) * N + col0 + nc]);
            int kp = kperm(kr);
            Bs[(nc + 0) * S + kp] = tf32f(v.x);
            Bs[(nc + 1) * S + kp] = tf32f(v.y);
            Bs[(nc + 2) * S + kp] = tf32f(v.z);
            Bs[(nc + 3) * S + kp] = tf32f(v.w);
        }
        __syncthreads();

#pragma unroll
        for (int ks = 0; ks < 2; ks++) {
            uint32_t af[2][4];
#pragma unroll
            for (int i = 0; i < 2; i++) {
                int rb = 32 * wm + 16 * i + g;
                float2 lo = *reinterpret_cast<float2*>(&As[rb * S + ks * 8 + 2 * tg]);
                float2 hi = *reinterpret_cast<float2*>(&As[(rb + 8) * S + ks * 8 + 2 * tg]);
                af[i][0] = __float_as_uint(lo.x);
                af[i][1] = __float_as_uint(hi.x);
                af[i][2] = __float_as_uint(lo.y);
                af[i][3] = __float_as_uint(hi.y);
            }
#pragma unroll
            for (int j = 0; j < 8; j++) {
                int nb = 64 * wn + 8 * j + g;
                float2 bv = *reinterpret_cast<float2*>(&Bs[nb * S + ks * 8 + 2 * tg]);
                uint32_t bf[2] = {__float_as_uint(bv.x), __float_as_uint(bv.y)};
                mma_tf32(acc[0][j], af[0], bf);
                mma_tf32(acc[1][j], af[1], bf);
            }
        }
        __syncthreads();
    }

    // =================== epilogues ===================
    if (MODE == 0) {
        if (blockIdx.x == 0) {
#pragma unroll
            for (int i = 0; i < 2; i++) {
                int rl = row0 + 32 * wm + 16 * i + g;
                int rh = rl + 8;
#pragma unroll
                for (int j = 0; j < 8; j++) {
                    int lc = 64 * wn + 8 * j + 2 * tg;
                    if (rl < M)
                        *reinterpret_cast<float2*>(&out[(size_t)rl * 128 + lc]) =
                            make_float2(acc[i][j][0], acc[i][j][1]);
                    if (rh < M)
                        *reinterpret_cast<float2*>(&out[(size_t)rh * 128 + lc]) =
                            make_float2(acc[i][j][2], acc[i][j][3]);
                }
            }
        } else {
            int coff = (blockIdx.x - 1) * 128;
#pragma unroll
            for (int i = 0; i < 2; i++) {
                int rl = row0 + 32 * wm + 16 * i + g;
                int rh = rl + 8;
#pragma unroll
                for (int j = 0; j < 8; j++) {
                    int lc = coff + 64 * wn + 8 * j + 2 * tg;
                    if (rl < M)
                        *reinterpret_cast<__half2*>(&outh[(size_t)rl * 256 + lc]) =
                            __floats2half2_rn(acc[i][j][0], acc[i][j][1]);
                    if (rh < M)
                        *reinterpret_cast<__half2*>(&outh[(size_t)rh * 256 + lc]) =
                            __floats2half2_rn(acc[i][j][2], acc[i][j][3]);
                }
            }
        }
    } else if (MODE == 1) {
#pragma unroll
        for (int i = 0; i < 2; i++) {
            int rl = row0 + 32 * wm + 16 * i + g;
            int rh = rl + 8;
#pragma unroll
            for (int j = 0; j < 8; j++) {
                int c = col0 + 64 * wn + 8 * j + 2 * tg;
                float2 bb = *reinterpret_cast<const float2*>(&bias[c]);
                float2 v0 = make_float2(fmaxf(acc[i][j][0] + bb.x, 0.f),
                                        fmaxf(acc[i][j][1] + bb.y, 0.f));
                float2 v1 = make_float2(fmaxf(acc[i][j][2] + bb.x, 0.f),
                                        fmaxf(acc[i][j][3] + bb.y, 0.f));
                if (rl < M) *reinterpret_cast<float2*>(&out[(size_t)rl * N + c]) = v0;
                if (rh < M) *reinterpret_cast<float2*>(&out[(size_t)rh * N + c]) = v1;
            }
        }
    } else {
        // MODE 2: bias + residual + LayerNorm (N == 128, grid.x == 1)
        float sl[2][2], s2l[2][2];
#pragma unroll
        for (int i = 0; i < 2; i++)
            for (int hf = 0; hf < 2; hf++) { sl[i][hf] = 0.f; s2l[i][hf] = 0.f; }

#pragma unroll
        for (int i = 0; i < 2; i++) {
            int rl = row0 + 32 * wm + 16 * i + g;
            int rh = rl + 8;
#pragma unroll
            for (int j = 0; j < 8; j++) {
                int c = 64 * wn + 8 * j + 2 * tg;
                float2 bb = *reinterpret_cast<const float2*>(&bias[c]);
                float2 r0 = make_float2(0.f, 0.f), r1 = make_float2(0.f, 0.f);
                if (rl < M) r0 = *reinterpret_cast<const float2*>(&res[(size_t)rl * 128 + c]);
                if (rh < M) r1 = *reinterpret_cast<const float2*>(&res[(size_t)rh * 128 + c]);
                acc[i][j][0] += bb.x + r0.x;
                acc[i][j][1] += bb.y + r0.y;
                acc[i][j][2] += bb.x + r1.x;
                acc[i][j][3] += bb.y + r1.y;
                sl[i][0]  += acc[i][j][0] + acc[i][j][1];
                s2l[i][0] += acc[i][j][0] * acc[i][j][0] + acc[i][j][1] * acc[i][j][1];
                sl[i][1]  += acc[i][j][2] + acc[i][j][3];
                s2l[i][1] += acc[i][j][2] * acc[i][j][2] + acc[i][j][3] * acc[i][j][3];
            }
        }
#pragma unroll
        for (int i = 0; i < 2; i++)
#pragma unroll
            for (int hf = 0; hf < 2; hf++) {
#pragma unroll
                for (int o = 1; o < 4; o <<= 1) {
                    sl[i][hf]  += __shfl_xor_sync(0xffffffffu, sl[i][hf],  o);
                    s2l[i][hf] += __shfl_xor_sync(0xffffffffu, s2l[i][hf], o);
                }
            }
        __syncthreads();
        float2* sbuf = reinterpret_cast<float2*>(sm);
        if (tg == 0) {
#pragma unroll
            for (int i = 0; i < 2; i++) {
                int rloc = 32 * wm + 16 * i + g;
                sbuf[wn * 128 + rloc]     = make_float2(sl[i][0], s2l[i][0]);
                sbuf[wn * 128 + rloc + 8] = make_float2(sl[i][1], s2l[i][1]);
            }
        }
        __syncthreads();
        float mu[2][2], rstd[2][2];
#pragma unroll
        for (int i = 0; i < 2; i++)
#pragma unroll
            for (int hf = 0; hf < 2; hf++) {
                int rloc = 32 * wm + 16 * i + g + hf * 8;
                float2 p0 = sbuf[rloc];
                float2 p1 = sbuf[128 + rloc];
                float s  = p0.x + p1.x;
                float s2 = p0.y + p1.y;
                float m  = s * (1.f / 128.f);
                float var = s2 * (1.f / 128.f) - m * m;
                mu[i][hf]   = m;
                rstd[i][hf] = rsqrtf(var + 1e-5f);
            }
#pragma unroll
        for (int i = 0; i < 2; i++) {
            int rl = row0 + 32 * wm + 16 * i + g;
            int rh = rl + 8;
#pragma unroll
            for (int j = 0; j < 8; j++) {
                int c = 64 * wn + 8 * j + 2 * tg;
                float2 gg = *reinterpret_cast<const float2*>(&lng[c]);
                float2 bb = *reinterpret_cast<const float2*>(&lnb[c]);
                if (rl < M) {
                    float2 o0;
                    o0.x = (acc[i][j][0] - mu[i][0]) * rstd[i][0] * gg.x + bb.x;
                    o0.y = (acc[i][j][1] - mu[i][0]) * rstd[i][0] * gg.y + bb.y;
                    *reinterpret_cast<float2*>(&out[(size_t)rl * 128 + c]) = o0;
                }
                if (rh < M) {
                    float2 o1;
                    o1.x = (acc[i][j][2] - mu[i][1]) * rstd[i][1] * gg.x + bb.x;
                    o1.y = (acc[i][j][3] - mu[i][1]) * rstd[i][1] * gg.y + bb.y;
                    *reinterpret_cast<float2*>(&out[(size_t)rh * 128 + c]) = o1;
                }
            }
        }
    }
}

// ---------------- binning: count / scan / scatter -----------------------------
__global__ void __launch_bounds__(256)
count_kernel(const int* __restrict__ dst, int* __restrict__ cnt) {
    int e = blockIdx.x * blockDim.x + threadIdx.x;
    if (e < NE) atomicAdd(&cnt[dst[e]], 1);
}

// scan writes off[] AND initializes cur[] = off[] (scatter uses cur as cursor)
__global__ void __launch_bounds__(1024)
scan_kernel(const int* __restrict__ cnt, int* __restrict__ off,
            int* __restrict__ cur) {
    __shared__ int s[1024];
    const int t  = threadIdx.x;
    const int CH = (NN + 1023) / 1024;
    const int base = t * CH;
    int sum = 0;
    for (int i = 0; i < CH; i++) {
        int idx = base + i;
        if (idx < NN) sum += cnt[idx];
    }
    s[t] = sum;
    __syncthreads();
    for (int o = 1; o < 1024; o <<= 1) {
        int v = (t >= o) ? s[t - o] : 0;
        __syncthreads();
        s[t] += v;
        __syncthreads();
    }
    int run = (t == 0) ? 0 : s[t - 1];
    for (int i = 0; i < CH; i++) {
        int idx = base + i;
        if (idx < NN) { off[idx] = run; cur[idx] = run; run += cnt[idx]; }
    }
    if (t == 1023) off[NN] = run;
}

__global__ void __launch_bounds__(256)
scatter_kernel(const int* __restrict__ src,
               const int* __restrict__ dst,
               int* __restrict__ cur,
               int* __restrict__ bin) {
    int e = blockIdx.x * blockDim.x + threadIdx.x;
    if (e >= NE) return;
    int pos = atomicAdd(&cur[dst[e]], 1);   // absolute position
    bin[pos] = src[e];
}

// ---------------- aggregation: 1 warp / node, fp16 KV, gather prefetch --------
// lanes 0-15: K·Q dots; lanes 16-31: V accumulate.
__global__ void __launch_bounds__(256)
agg_kernel(const int* __restrict__ off,
           const int* __restrict__ bin,
           const float* __restrict__ Q,
           const __half* __restrict__ KV,
           float* __restrict__ head_out) {
    int n = (blockIdx.x * blockDim.x + threadIdx.x) >> 5;
    if (n >= NN) return;
    const int lane = threadIdx.x & 31;
    const int l16  = lane & 15;
    const int srcl = l16 & ~1;          // even lane of the head pair
    int beg = off[n], end = off[n + 1];

    float q[8];
    if (lane < 16) {
        float4 qa = *reinterpret_cast<const float4*>(&Q[(size_t)n * D + 8 * l16]);
        float4 qb = *reinterpret_cast<const float4*>(&Q[(size_t)n * D + 8 * l16 + 4]);
        q[0] = qa.x; q[1] = qa.y; q[2] = qa.z; q[3] = qa.w;
        q[4] = qb.x; q[5] = qb.y; q[6] = qb.z; q[7] = qb.w;
    }

    float acc[8];
#pragma unroll
    for (int j = 0; j < 8; j++) acc[j] = 0.f;
    float zt = 0.f;

    auto process = [&](const uint4& raw) {
        float2 a0 = __half22float2(*reinterpret_cast<const __half2*>(&raw.x));
        float2 a1 = __half22float2(*reinterpret_cast<const __half2*>(&raw.y));
        float2 a2 = __half22float2(*reinterpret_cast<const __half2*>(&raw.z));
        float2 a3 = __half22float2(*reinterpret_cast<const __half2*>(&raw.w));
        float p = a0.x * q[0] + a0.y * q[1] + a1.x * q[2] + a1.y * q[3]
                + a2.x * q[4] + a2.y * q[5] + a3.x * q[6] + a3.y * q[7];
        p += __shfl_xor_sync(0xffffffffu, p, 1);
        float sc = __expf(fminf(5.f, fmaxf(-5.f, p * 0.25f)));
        zt += sc;
        float sv = __shfl_sync(0xffffffffu, sc, srcl);
        if (lane >= 16) {
            acc[0] += a0.x * sv; acc[1] += a0.y * sv;
            acc[2] += a1.x * sv; acc[3] += a1.y * sv;
            acc[4] += a2.x * sv; acc[5] += a2.y * sv;
            acc[6] += a3.x * sv; acc[7] += a3.y * sv;
        }
    };

    if (beg < end) {
        int s0 = bin[beg];
        uint4 raw = *reinterpret_cast<const uint4*>(KV + (size_t)s0 * 256 + lane * 8);
        for (int i = beg; i + 1 < end; i++) {
            int sn = bin[i + 1];
            uint4 rawn = *reinterpret_cast<const uint4*>(KV + (size_t)sn * 256 + lane * 8);
            process(raw);
            raw = rawn;
        }
        process(raw);
    }

    float ztv = __shfl_sync(0xffffffffu, zt, srcl);
    if (lane >= 16) {
        if (ztv > 0.f) {
            float inv = 1.f / ztv;
#pragma unroll
            for (int j = 0; j < 8; j++) acc[j] *= inv;
        }
        float* op = head_out + (size_t)n * D + 8 * l16;
        *reinterpret_cast<float4*>(op)     = make_float4(acc[0], acc[1], acc[2], acc[3]);
        *reinterpret_cast<float4*>(op + 4) = make_float4(acc[4], acc[5], acc[6], acc[7]);
    }
}

// ---------------- launch -----------------------------------------------------
extern "C" void kernel_launch(void* const* d_in, const int* in_sizes, int n_in,
                              void* d_out, int out_size) {
    const float* h   = (const float*)d_in[0];
    const int*   src = (const int*)  d_in[1];
    const int*   dst = (const int*)  d_in[2];
    const float* Wq  = (const float*)d_in[3];
    const float* Wk  = (const float*)d_in[4];
    const float* Wv  = (const float*)d_in[5];
    const float* Wo  = (const float*)d_in[6];
    const float* bo  = (const float*)d_in[7];
    const float* g1  = (const float*)d_in[8];
    const float* b1  = (const float*)d_in[9];
    const float* g2  = (const float*)d_in[10];
    const float* b2  = (const float*)d_in[11];
    const float* W1  = (const float*)d_in[12];
    const float* c1  = (const float*)d_in[13];
    const float* W2  = (const float*)d_in[14];
    const float* c2  = (const float*)d_in[15];
    float* out = (float*)d_out;

    float *Qp, *Wpkp, *wVp, *hhp, *tp;
    __half* KVp;
    int *cntp, *offp, *curp, *binp;
    cudaGetSymbolAddress((void**)&Qp,   g_Q);
    cudaGetSymbolAddress((void**)&KVp,  g_KVh);
    cudaGetSymbolAddress((void**)&Wpkp, g_Wpk);
    cudaGetSymbolAddress((void**)&wVp,  g_wV);
    cudaGetSymbolAddress((void**)&hhp,  g_hh);
    cudaGetSymbolAddress((void**)&tp,   g_t);
    cudaGetSymbolAddress((void**)&cntp, g_cnt);
    cudaGetSymbolAddress((void**)&offp, g_off);
    cudaGetSymbolAddress((void**)&curp, g_cur);
    cudaGetSymbolAddress((void**)&binp, g_bin);

    const int GY = (NN + 127) / 128;   // 782

    // --- binning by dst ---
    cudaMemsetAsync(cntp, 0, NN * sizeof(int));
    count_kernel<<<(NE + 255) / 256, 256>>>(dst, cntp);
    scan_kernel<<<1, 1024>>>(cntp, offp, curp);
    scatter_kernel<<<(NE + 255) / 256, 256>>>(src, dst, curp, binp);

    // --- fused QKV GEMM (tf32), Q fp32 + KV fp16 outputs ---
    packW_kernel<<<(D * D + 255) / 256, 256>>>(Wq, Wk, Wv, Wpkp);
    mma_gemm<0><<<dim3(3, GY), 256>>>(h, Wpkp, nullptr, nullptr, nullptr, nullptr,
                                      Qp, KVp, NN, 3 * D, D);

    // --- attention aggregation (atomic-free, fp16 gathers, pipelined) ---
    {
        int blocks = (NN * 32 + 255) / 256;
        agg_kernel<<<blocks, 256>>>(offp, binp, Qp, KVp, wVp);
    }

    // hh = LN(h + head_out @ Wo + bo)
    mma_gemm<2><<<dim3(1, GY), 256>>>(wVp, Wo, bo, h, g1, b1,
                                      hhp, nullptr, NN, D, D);

    // t = relu(hh @ W1 + c1), fp32
    mma_gemm<1><<<dim3(2, GY), 256>>>(hhp, W1, c1, nullptr, nullptr, nullptr,
                                      tp, nullptr, NN, 2 * D, D);

    // out = LN(hh + t @ W2 + c2)
    mma_gemm<2><<<dim3(1, GY), 256>>>(tp, W2, c2, hhp, g2, b2,
                                      out, nullptr, NN, D, 2 * D);
}

// round 13
// speedup vs baseline: 1.1971x; 1.1971x over previous
#include <cuda_runtime.h>
#include <cuda_fp16.h>
#include <cstdint>

constexpr int NN = 100000;   // nodes
constexpr int NE = 1600000;  // edges
constexpr int D  = 128;
// H=8, DH=16, scale=0.25

// ---------------- scratch ----------------------------------------------------
__device__ float  g_Q  [NN * D];        // Q rows fp32 (streamed in agg)
__device__ __half g_KVh[NN * 2 * D];    // per node: [K(128) | V(128)] fp16 (gathered)
__device__ float  g_Wpk[D * 3 * D];     // packed weights [k][Wq|Wk|Wv]
__device__ float  g_wV [NN * D];        // head_out
__device__ float  g_hh [NN * D];
__device__ float  g_t  [NN * 2 * D];    // FFN intermediate fp32
__device__ int    g_cnt[NN];            // zero-initialized; scan re-zeroes each pass
__device__ int    g_off[NN + 1];
__device__ int    g_cur[NN];
__device__ int    g_bin[NE];            // src ids binned by dst

// ---------------- helpers -----------------------------------------------------
__device__ __forceinline__ void mma_tf32(float* d, const uint32_t* a, const uint32_t* b) {
    asm volatile(
        "mma.sync.aligned.m16n8k8.row.col.f32.tf32.tf32.f32 "
        "{%0,%1,%2,%3}, {%4,%5,%6,%7}, {%8,%9}, {%0,%1,%2,%3};"
        : "+f"(d[0]), "+f"(d[1]), "+f"(d[2]), "+f"(d[3])
        : "r"(a[0]), "r"(a[1]), "r"(a[2]), "r"(a[3]), "r"(b[0]), "r"(b[1]));
}

__device__ __forceinline__ void cpa16(uint32_t dst, const void* src, int sz) {
    asm volatile("cp.async.ca.shared.global [%0], [%1], 16, %2;"
                 :: "r"(dst), "l"(src), "r"(sz));
}
__device__ __forceinline__ void cpa_commit() {
    asm volatile("cp.async.commit_group;");
}
template <int N_>
__device__ __forceinline__ void cpa_wait() {
    asm volatile("cp.async.wait_group %0;" :: "n"(N_));
}

// ---------------- pack Wq|Wk|Wv into [128 x 384] -----------------------------
__global__ void __launch_bounds__(256)
packW_kernel(const float* __restrict__ Wq,
             const float* __restrict__ Wk,
             const float* __restrict__ Wv,
             float* __restrict__ P) {
    int i = blockIdx.x * blockDim.x + threadIdx.x;
    if (i >= D * D) return;
    int k = i / D, c = i % D;
    P[(size_t)k * (3 * D) + c]         = Wq[i];
    P[(size_t)k * (3 * D) + D + c]     = Wk[i];
    P[(size_t)k * (3 * D) + 2 * D + c] = Wv[i];
}

// ========== tf32 tensor-core GEMM, BM=BN=128, BK=16, cp.async 2-stage =========
// A fp32 [M,K]; B fp32 [K,N]. HW truncates fp32->tf32 inside HMMA (no cvt).
// MODE 0: QKV split store (out=Q fp32 stride 128; outh=KV fp16 stride 256)
// MODE 1: out = relu(A@B + bias), fp32, generic N (grid.x = N/128)
// MODE 2: out = LN(res + A@B + bias)*lng + lnb, N==128, grid.x==1
template <int MODE>
__global__ void __launch_bounds__(256, 2)
mma_gemm(const float* __restrict__ A, const float* __restrict__ B,
         const float* __restrict__ bias, const float* __restrict__ res,
         const float* __restrict__ lng, const float* __restrict__ lnb,
         float* __restrict__ out, __half* __restrict__ outh,
         int M, int N, int K) {
    constexpr int SA = 20;    // A smem stride (floats): conflict-free, 16B-multiple rows? (80B, 16B-aligned)
    constexpr int SB = 136;   // B smem stride (floats): 544B, 16B-aligned
    __shared__ __align__(16) float As[2][128 * SA];
    __shared__ __align__(16) float Bs[2][16 * SB];

    const int tid  = threadIdx.x;
    const int warp = tid >> 5;
    const int lane = tid & 31;
    const int g    = lane >> 2;
    const int tg   = lane & 3;
    const int wm   = warp & 3;
    const int wn   = warp >> 2;
    const int row0 = blockIdx.y * 128;
    const int col0 = blockIdx.x * 128;

    float acc[2][8][4];
#pragma unroll
    for (int i = 0; i < 2; i++)
#pragma unroll
        for (int j = 0; j < 8; j++)
#pragma unroll
            for (int q = 0; q < 4; q++) acc[i][j][q] = 0.f;

    // A-chunk mapping: 512 chunks of 16B; chunk c -> row m=c>>2, kc=(c&3)*4
    const int am  = tid >> 1;              // rows: 2 chunks per thread -> handled via l loop
    // (we use generic c = tid + 256*l below)

    auto load_tile = [&](int kt, int st) {
        const int k0 = kt * 16;
#pragma unroll
        for (int l = 0; l < 2; l++) {
            int c  = tid + 256 * l;
            int m  = c >> 2;
            int kc = (c & 3) * 4;
            const float* srcA = A + (size_t)(row0 + m) * K + k0 + kc;
            int sz = (row0 + m < M) ? 16 : 0;
            uint32_t dstA = (uint32_t)__cvta_generic_to_shared(&As[st][m * SA + kc]);
            cpa16(dstA, srcA, sz);
        }
#pragma unroll
        for (int l = 0; l < 2; l++) {
            int c  = tid + 256 * l;
            int kr = c >> 5;
            int nc = (c & 31) * 4;
            const float* srcB = B + (size_t)(k0 + kr) * N + col0 + nc;
            uint32_t dstB = (uint32_t)__cvta_generic_to_shared(&Bs[st][kr * SB + nc]);
            cpa16(dstB, srcB, 16);
        }
    };

    const int T = K / 16;
    load_tile(0, 0);
    cpa_commit();

    for (int t = 0; t < T; t++) {
        const int st = t & 1;
        if (t + 1 < T) {
            load_tile(t + 1, (t + 1) & 1);
            cpa_commit();
            cpa_wait<1>();
        } else {
            cpa_wait<0>();
        }
        __syncthreads();

#pragma unroll
        for (int ks = 0; ks < 2; ks++) {
            const int kk = ks * 8;
            uint32_t af[2][4];
#pragma unroll
            for (int i = 0; i < 2; i++) {
                int rb = 32 * wm + 16 * i + g;
                af[i][0] = __float_as_uint(As[st][rb * SA + kk + tg]);
                af[i][1] = __float_as_uint(As[st][(rb + 8) * SA + kk + tg]);
                af[i][2] = __float_as_uint(As[st][rb * SA + kk + tg + 4]);
                af[i][3] = __float_as_uint(As[st][(rb + 8) * SA + kk + tg + 4]);
            }
#pragma unroll
            for (int j = 0; j < 8; j++) {
                int nb = 64 * wn + 8 * j + g;
                uint32_t bf[2];
                bf[0] = __float_as_uint(Bs[st][(kk + tg) * SB + nb]);
                bf[1] = __float_as_uint(Bs[st][(kk + tg + 4) * SB + nb]);
                mma_tf32(acc[0][j], af[0], bf);
                mma_tf32(acc[1][j], af[1], bf);
            }
        }
        __syncthreads();
    }

    // =================== epilogues ===================
    if (MODE == 0) {
        if (blockIdx.x == 0) {
#pragma unroll
            for (int i = 0; i < 2; i++) {
                int rl = row0 + 32 * wm + 16 * i + g;
                int rh = rl + 8;
#pragma unroll
                for (int j = 0; j < 8; j++) {
                    int lc = 64 * wn + 8 * j + 2 * tg;
                    // columns 2*tg within the 8-block? fragment holds n = g... NOTE:
                    // acc col mapping: thread holds cols {2*tg, 2*tg+1} of n-block j.
                    if (rl < M)
                        *reinterpret_cast<float2*>(&out[(size_t)rl * 128 + lc]) =
                            make_float2(acc[i][j][0], acc[i][j][1]);
                    if (rh < M)
                        *reinterpret_cast<float2*>(&out[(size_t)rh * 128 + lc]) =
                            make_float2(acc[i][j][2], acc[i][j][3]);
                }
            }
        } else {
            int coff = (blockIdx.x - 1) * 128;
#pragma unroll
            for (int i = 0; i < 2; i++) {
                int rl = row0 + 32 * wm + 16 * i + g;
                int rh = rl + 8;
#pragma unroll
                for (int j = 0; j < 8; j++) {
                    int lc = coff + 64 * wn + 8 * j + 2 * tg;
                    if (rl < M)
                        *reinterpret_cast<__half2*>(&outh[(size_t)rl * 256 + lc]) =
                            __floats2half2_rn(acc[i][j][0], acc[i][j][1]);
                    if (rh < M)
                        *reinterpret_cast<__half2*>(&outh[(size_t)rh * 256 + lc]) =
                            __floats2half2_rn(acc[i][j][2], acc[i][j][3]);
                }
            }
        }
    } else if (MODE == 1) {
#pragma unroll
        for (int i = 0; i < 2; i++) {
            int rl = row0 + 32 * wm + 16 * i + g;
            int rh = rl + 8;
#pragma unroll
            for (int j = 0; j < 8; j++) {
                int c = col0 + 64 * wn + 8 * j + 2 * tg;
                float2 bb = *reinterpret_cast<const float2*>(&bias[c]);
                float2 v0 = make_float2(fmaxf(acc[i][j][0] + bb.x, 0.f),
                                        fmaxf(acc[i][j][1] + bb.y, 0.f));
                float2 v1 = make_float2(fmaxf(acc[i][j][2] + bb.x, 0.f),
                                        fmaxf(acc[i][j][3] + bb.y, 0.f));
                if (rl < M) *reinterpret_cast<float2*>(&out[(size_t)rl * N + c]) = v0;
                if (rh < M) *reinterpret_cast<float2*>(&out[(size_t)rh * N + c]) = v1;
            }
        }
    } else {
        // MODE 2: bias + residual + LayerNorm (N == 128, grid.x == 1)
        float sl[2][2], s2l[2][2];
#pragma unroll
        for (int i = 0; i < 2; i++)
            for (int hf = 0; hf < 2; hf++) { sl[i][hf] = 0.f; s2l[i][hf] = 0.f; }

#pragma unroll
        for (int i = 0; i < 2; i++) {
            int rl = row0 + 32 * wm + 16 * i + g;
            int rh = rl + 8;
#pragma unroll
            for (int j = 0; j < 8; j++) {
                int c = 64 * wn + 8 * j + 2 * tg;
                float2 bb = *reinterpret_cast<const float2*>(&bias[c]);
                float2 r0 = make_float2(0.f, 0.f), r1 = make_float2(0.f, 0.f);
                if (rl < M) r0 = *reinterpret_cast<const float2*>(&res[(size_t)rl * 128 + c]);
                if (rh < M) r1 = *reinterpret_cast<const float2*>(&res[(size_t)rh * 128 + c]);
                acc[i][j][0] += bb.x + r0.x;
                acc[i][j][1] += bb.y + r0.y;
                acc[i][j][2] += bb.x + r1.x;
                acc[i][j][3] += bb.y + r1.y;
                sl[i][0]  += acc[i][j][0] + acc[i][j][1];
                s2l[i][0] += acc[i][j][0] * acc[i][j][0] + acc[i][j][1] * acc[i][j][1];
                sl[i][1]  += acc[i][j][2] + acc[i][j][3];
                s2l[i][1] += acc[i][j][2] * acc[i][j][2] + acc[i][j][3] * acc[i][j][3];
            }
        }
#pragma unroll
        for (int i = 0; i < 2; i++)
#pragma unroll
            for (int hf = 0; hf < 2; hf++) {
#pragma unroll
                for (int o = 1; o < 4; o <<= 1) {
                    sl[i][hf]  += __shfl_xor_sync(0xffffffffu, sl[i][hf],  o);
                    s2l[i][hf] += __shfl_xor_sync(0xffffffffu, s2l[i][hf], o);
                }
            }
        __syncthreads();
        float2* sbuf = reinterpret_cast<float2*>(&As[0][0]);
        if (tg == 0) {
#pragma unroll
            for (int i = 0; i < 2; i++) {
                int rloc = 32 * wm + 16 * i + g;
                sbuf[wn * 128 + rloc]     = make_float2(sl[i][0], s2l[i][0]);
                sbuf[wn * 128 + rloc + 8] = make_float2(sl[i][1], s2l[i][1]);
            }
        }
        __syncthreads();
        float mu[2][2], rstd[2][2];
#pragma unroll
        for (int i = 0; i < 2; i++)
#pragma unroll
            for (int hf = 0; hf < 2; hf++) {
                int rloc = 32 * wm + 16 * i + g + hf * 8;
                float2 p0 = sbuf[rloc];
                float2 p1 = sbuf[128 + rloc];
                float s  = p0.x + p1.x;
                float s2 = p0.y + p1.y;
                float m  = s * (1.f / 128.f);
                float var = s2 * (1.f / 128.f) - m * m;
                mu[i][hf]   = m;
                rstd[i][hf] = rsqrtf(var + 1e-5f);
            }
#pragma unroll
        for (int i = 0; i < 2; i++) {
            int rl = row0 + 32 * wm + 16 * i + g;
            int rh = rl + 8;
#pragma unroll
            for (int j = 0; j < 8; j++) {
                int c = 64 * wn + 8 * j + 2 * tg;
                float2 gg = *reinterpret_cast<const float2*>(&lng[c]);
                float2 bb = *reinterpret_cast<const float2*>(&lnb[c]);
                if (rl < M) {
                    float2 o0;
                    o0.x = (acc[i][j][0] - mu[i][0]) * rstd[i][0] * gg.x + bb.x;
                    o0.y = (acc[i][j][1] - mu[i][0]) * rstd[i][0] * gg.y + bb.y;
                    *reinterpret_cast<float2*>(&out[(size_t)rl * 128 + c]) = o0;
                }
                if (rh < M) {
                    float2 o1;
                    o1.x = (acc[i][j][2] - mu[i][1]) * rstd[i][1] * gg.x + bb.x;
                    o1.y = (acc[i][j][3] - mu[i][1]) * rstd[i][1] * gg.y + bb.y;
                    *reinterpret_cast<float2*>(&out[(size_t)rh * 128 + c]) = o1;
                }
            }
        }
    }
}

// ---------------- binning: count / scan / scatter -----------------------------
__global__ void __launch_bounds__(256)
count_kernel(const int* __restrict__ dst, int* __restrict__ cnt) {
    int e = blockIdx.x * blockDim.x + threadIdx.x;
    if (e < NE) atomicAdd(&cnt[dst[e]], 1);
}

// scan: off[] = exclusive prefix of cnt; cur[] = off[]; cnt[] reset to 0
// (cnt starts zero-initialized; re-zeroing here keeps every graph replay identical)
__global__ void __launch_bounds__(1024)
scan_kernel(int* __restrict__ cnt, int* __restrict__ off, int* __restrict__ cur) {
    __shared__ int s[1024];
    const int t  = threadIdx.x;
    const int CH = (NN + 1023) / 1024;
    const int base = t * CH;
    int sum = 0;
    for (int i = 0; i < CH; i++) {
        int idx = base + i;
        if (idx < NN) sum += cnt[idx];
    }
    s[t] = sum;
    __syncthreads();
    for (int o = 1; o < 1024; o <<= 1) {
        int v = (t >= o) ? s[t - o] : 0;
        __syncthreads();
        s[t] += v;
        __syncthreads();
    }
    int run = (t == 0) ? 0 : s[t - 1];
    for (int i = 0; i < CH; i++) {
        int idx = base + i;
        if (idx < NN) {
            int c = cnt[idx];
            off[idx] = run; cur[idx] = run;
            run += c;
            cnt[idx] = 0;
        }
    }
    if (t == 1023) off[NN] = run;
}

__global__ void __launch_bounds__(256)
scatter_kernel(const int* __restrict__ src,
               const int* __restrict__ dst,
               int* __restrict__ cur,
               int* __restrict__ bin) {
    int e = blockIdx.x * blockDim.x + threadIdx.x;
    if (e >= NE) return;
    int pos = atomicAdd(&cur[dst[e]], 1);
    bin[pos] = src[e];
}

// ---------------- aggregation: 1 warp / node, fp16 KV, gather prefetch --------
__global__ void __launch_bounds__(256)
agg_kernel(const int* __restrict__ off,
           const int* __restrict__ bin,
           const float* __restrict__ Q,
           const __half* __restrict__ KV,
           float* __restrict__ head_out) {
    int n = (blockIdx.x * blockDim.x + threadIdx.x) >> 5;
    if (n >= NN) return;
    const int lane = threadIdx.x & 31;
    const int l16  = lane & 15;
    const int srcl = l16 & ~1;
    int beg = off[n], end = off[n + 1];

    float q[8];
    if (lane < 16) {
        float4 qa = *reinterpret_cast<const float4*>(&Q[(size_t)n * D + 8 * l16]);
        float4 qb = *reinterpret_cast<const float4*>(&Q[(size_t)n * D + 8 * l16 + 4]);
        q[0] = qa.x; q[1] = qa.y; q[2] = qa.z; q[3] = qa.w;
        q[4] = qb.x; q[5] = qb.y; q[6] = qb.z; q[7] = qb.w;
    }

    float acc[8];
#pragma unroll
    for (int j = 0; j < 8; j++) acc[j] = 0.f;
    float zt = 0.f;

    auto process = [&](const uint4& raw) {
        float2 a0 = __half22float2(*reinterpret_cast<const __half2*>(&raw.x));
        float2 a1 = __half22float2(*reinterpret_cast<const __half2*>(&raw.y));
        float2 a2 = __half22float2(*reinterpret_cast<const __half2*>(&raw.z));
        float2 a3 = __half22float2(*reinterpret_cast<const __half2*>(&raw.w));
        float p = a0.x * q[0] + a0.y * q[1] + a1.x * q[2] + a1.y * q[3]
                + a2.x * q[4] + a2.y * q[5] + a3.x * q[6] + a3.y * q[7];
        p += __shfl_xor_sync(0xffffffffu, p, 1);
        float sc = __expf(fminf(5.f, fmaxf(-5.f, p * 0.25f)));
        zt += sc;
        float sv = __shfl_sync(0xffffffffu, sc, srcl);
        if (lane >= 16) {
            acc[0] += a0.x * sv; acc[1] += a0.y * sv;
            acc[2] += a1.x * sv; acc[3] += a1.y * sv;
            acc[4] += a2.x * sv; acc[5] += a2.y * sv;
            acc[6] += a3.x * sv; acc[7] += a3.y * sv;
        }
    };

    if (beg < end) {
        int s0 = bin[beg];
        uint4 raw = *reinterpret_cast<const uint4*>(KV + (size_t)s0 * 256 + lane * 8);
        for (int i = beg; i + 1 < end; i++) {
            int sn = bin[i + 1];
            uint4 rawn = *reinterpret_cast<const uint4*>(KV + (size_t)sn * 256 + lane * 8);
            process(raw);
            raw = rawn;
        }
        process(raw);
    }

    float ztv = __shfl_sync(0xffffffffu, zt, srcl);
    if (lane >= 16) {
        if (ztv > 0.f) {
            float inv = 1.f / ztv;
#pragma unroll
            for (int j = 0; j < 8; j++) acc[j] *= inv;
        }
        float* op = head_out + (size_t)n * D + 8 * l16;
        *reinterpret_cast<float4*>(op)     = make_float4(acc[0], acc[1], acc[2], acc[3]);
        *reinterpret_cast<float4*>(op + 4) = make_float4(acc[4], acc[5], acc[6], acc[7]);
    }
}

// ---------------- launch -----------------------------------------------------
extern "C" void kernel_launch(void* const* d_in, const int* in_sizes, int n_in,
                              void* d_out, int out_size) {
    const float* h   = (const float*)d_in[0];
    const int*   src = (const int*)  d_in[1];
    const int*   dst = (const int*)  d_in[2];
    const float* Wq  = (const float*)d_in[3];
    const float* Wk  = (const float*)d_in[4];
    const float* Wv  = (const float*)d_in[5];
    const float* Wo  = (const float*)d_in[6];
    const float* bo  = (const float*)d_in[7];
    const float* g1  = (const float*)d_in[8];
    const float* b1  = (const float*)d_in[9];
    const float* g2  = (const float*)d_in[10];
    const float* b2  = (const float*)d_in[11];
    const float* W1  = (const float*)d_in[12];
    const float* c1  = (const float*)d_in[13];
    const float* W2  = (const float*)d_in[14];
    const float* c2  = (const float*)d_in[15];
    float* out = (float*)d_out;

    float *Qp, *Wpkp, *wVp, *hhp, *tp;
    __half* KVp;
    int *cntp, *offp, *curp, *binp;
    cudaGetSymbolAddress((void**)&Qp,   g_Q);
    cudaGetSymbolAddress((void**)&KVp,  g_KVh);
    cudaGetSymbolAddress((void**)&Wpkp, g_Wpk);
    cudaGetSymbolAddress((void**)&wVp,  g_wV);
    cudaGetSymbolAddress((void**)&hhp,  g_hh);
    cudaGetSymbolAddress((void**)&tp,   g_t);
    cudaGetSymbolAddress((void**)&cntp, g_cnt);
    cudaGetSymbolAddress((void**)&offp, g_off);
    cudaGetSymbolAddress((void**)&curp, g_cur);
    cudaGetSymbolAddress((void**)&binp, g_bin);

    const int GY = (NN + 127) / 128;   // 782

    // --- binning by dst (no memsets: cnt self-zeroing via scan) ---
    count_kernel<<<(NE + 255) / 256, 256>>>(dst, cntp);
    scan_kernel<<<1, 1024>>>(cntp, offp, curp);
    scatter_kernel<<<(NE + 255) / 256, 256>>>(src, dst, curp, binp);

    // --- fused QKV GEMM (tf32 cp.async pipeline), Q fp32 + KV fp16 outputs ---
    packW_kernel<<<(D * D + 255) / 256, 256>>>(Wq, Wk, Wv, Wpkp);
    mma_gemm<0><<<dim3(3, GY), 256>>>(h, Wpkp, nullptr, nullptr, nullptr, nullptr,
                                      Qp, KVp, NN, 3 * D, D);

    // --- attention aggregation (atomic-free, fp16 gathers, pipelined) ---
    {
        int blocks = (NN * 32 + 255) / 256;
        agg_kernel<<<blocks, 256>>>(offp, binp, Qp, KVp, wVp);
    }

    // hh = LN(h + head_out @ Wo + bo)
    mma_gemm<2><<<dim3(1, GY), 256>>>(wVp, Wo, bo, h, g1, b1,
                                      hhp, nullptr, NN, D, D);

    // t = relu(hh @ W1 + c1)
    mma_gemm<1><<<dim3(2, GY), 256>>>(hhp, W1, c1, nullptr, nullptr, nullptr,
                                      tp, nullptr, NN, 2 * D, D);

    // out = LN(hh + t @ W2 + c2)
    mma_gemm<2><<<dim3(1, GY), 256>>>(tp, W2, c2, hhp, g2, b2,
                                      out, nullptr, NN, D, 2 * D);
}

// round 14
// speedup vs baseline: 1.2184x; 1.0178x over previous
#include <cuda_runtime.h>
#include <cuda_fp16.h>
#include <cstdint>

constexpr int NN = 100000;   // nodes
constexpr int NE = 1600000;  // edges
constexpr int D  = 128;
// H=8, DH=16, scale=0.25

// ---------------- scratch ----------------------------------------------------
__device__ float  g_Q  [NN * D];        // Q rows fp32 (streamed in agg)
__device__ __half g_KVh[NN * 2 * D];    // per node: [K(128) | V(128)] fp16 (gathered)
__device__ float  g_Wpk[D * 3 * D];     // packed weights [k][Wq|Wk|Wv]
__device__ float  g_wV [NN * D];        // head_out
__device__ float  g_hh [NN * D];
__device__ float  g_t  [NN * 2 * D];    // FFN intermediate fp32
__device__ int    g_cnt[NN];            // zero-init; scan re-zeroes each pass
__device__ int    g_off[NN + 1];
__device__ int    g_cur[NN];
__device__ int    g_bin[NE];            // src ids binned by dst

// ---------------- helpers -----------------------------------------------------
__device__ __forceinline__ void mma_tf32(float* d, const uint32_t* a, const uint32_t* b) {
    asm volatile(
        "mma.sync.aligned.m16n8k8.row.col.f32.tf32.tf32.f32 "
        "{%0,%1,%2,%3}, {%4,%5,%6,%7}, {%8,%9}, {%0,%1,%2,%3};"
        : "+f"(d[0]), "+f"(d[1]), "+f"(d[2]), "+f"(d[3])
        : "r"(a[0]), "r"(a[1]), "r"(a[2]), "r"(a[3]), "r"(b[0]), "r"(b[1]));
}

__device__ __forceinline__ void cpa16(uint32_t dst, const void* src, int sz) {
    asm volatile("cp.async.ca.shared.global [%0], [%1], 16, %2;"
                 :: "r"(dst), "l"(src), "r"(sz));
}
__device__ __forceinline__ void cpa_commit() {
    asm volatile("cp.async.commit_group;");
}
template <int N_>
__device__ __forceinline__ void cpa_wait() {
    asm volatile("cp.async.wait_group %0;" :: "n"(N_));
}

// ---------------- pack Wq|Wk|Wv into [128 x 384] -----------------------------
__global__ void __launch_bounds__(256)
packW_kernel(const float* __restrict__ Wq,
             const float* __restrict__ Wk,
             const float* __restrict__ Wv,
             float* __restrict__ P) {
    int i = blockIdx.x * blockDim.x + threadIdx.x;
    if (i >= D * D) return;
    int k = i / D, c = i % D;
    P[(size_t)k * (3 * D) + c]         = Wq[i];
    P[(size_t)k * (3 * D) + D + c]     = Wk[i];
    P[(size_t)k * (3 * D) + 2 * D + c] = Wv[i];
}

// ====== tf32 tensor-core GEMM, BM=BN=128, BK=16, cp.async 3-stage pipeline ====
// MODE 0: QKV split store (out=Q fp32 stride 128; outh=KV fp16 stride 256)
// MODE 1: out = relu(A@B + bias), fp32, generic N (grid.x = N/128)
// MODE 2: out = LN(res + A@B + bias)*lng + lnb, N==128, grid.x==1
template <int MODE>
__global__ void __launch_bounds__(256, 2)
mma_gemm(const float* __restrict__ A, const float* __restrict__ B,
         const float* __restrict__ bias, const float* __restrict__ res,
         const float* __restrict__ lng, const float* __restrict__ lnb,
         float* __restrict__ out, __half* __restrict__ outh,
         int M, int N, int K) {
    constexpr int SA = 20;    // A smem stride (floats)
    constexpr int SB = 136;   // B smem stride (floats)
    constexpr int ST = 3;     // pipeline stages
    __shared__ __align__(16) float As[ST][128 * SA];
    __shared__ __align__(16) float Bs[ST][16 * SB];

    const int tid  = threadIdx.x;
    const int warp = tid >> 5;
    const int lane = tid & 31;
    const int g    = lane >> 2;
    const int tg   = lane & 3;
    const int wm   = warp & 3;
    const int wn   = warp >> 2;
    const int row0 = blockIdx.y * 128;
    const int col0 = blockIdx.x * 128;

    float acc[2][8][4];
#pragma unroll
    for (int i = 0; i < 2; i++)
#pragma unroll
        for (int j = 0; j < 8; j++)
#pragma unroll
            for (int q = 0; q < 4; q++) acc[i][j][q] = 0.f;

    auto load_tile = [&](int kt, int st) {
        const int k0 = kt * 16;
#pragma unroll
        for (int l = 0; l < 2; l++) {
            int c  = tid + 256 * l;
            int m  = c >> 2;
            int kc = (c & 3) * 4;
            const float* srcA = A + (size_t)(row0 + m) * K + k0 + kc;
            int sz = (row0 + m < M) ? 16 : 0;
            uint32_t dstA = (uint32_t)__cvta_generic_to_shared(&As[st][m * SA + kc]);
            cpa16(dstA, srcA, sz);
        }
#pragma unroll
        for (int l = 0; l < 2; l++) {
            int c  = tid + 256 * l;
            int kr = c >> 5;
            int nc = (c & 31) * 4;
            const float* srcB = B + (size_t)(k0 + kr) * N + col0 + nc;
            uint32_t dstB = (uint32_t)__cvta_generic_to_shared(&Bs[st][kr * SB + nc]);
            cpa16(dstB, srcB, 16);
        }
    };

    const int T = K / 16;
    load_tile(0, 0);
    cpa_commit();
    if (T > 1) { load_tile(1, 1); cpa_commit(); }

    for (int t = 0; t < T; t++) {
        const int st = t % ST;
        if (t + 1 < T) cpa_wait<1>();   // tile t landed (tile t+1 may be pending)
        else           cpa_wait<0>();
        __syncthreads();                // all warps done with stage st's previous use
        if (t + 2 < T) {                // issue AFTER barrier: safe stage reuse at ST=3
            load_tile(t + 2, (t + 2) % ST);
            cpa_commit();
        }

#pragma unroll
        for (int ks = 0; ks < 2; ks++) {
            const int kk = ks * 8;
            uint32_t af[2][4];
#pragma unroll
            for (int i = 0; i < 2; i++) {
                int rb = 32 * wm + 16 * i + g;
                af[i][0] = __float_as_uint(As[st][rb * SA + kk + tg]);
                af[i][1] = __float_as_uint(As[st][(rb + 8) * SA + kk + tg]);
                af[i][2] = __float_as_uint(As[st][rb * SA + kk + tg + 4]);
                af[i][3] = __float_as_uint(As[st][(rb + 8) * SA + kk + tg + 4]);
            }
#pragma unroll
            for (int j = 0; j < 8; j++) {
                int nb = 64 * wn + 8 * j + g;
                uint32_t bf[2];
                bf[0] = __float_as_uint(Bs[st][(kk + tg) * SB + nb]);
                bf[1] = __float_as_uint(Bs[st][(kk + tg + 4) * SB + nb]);
                mma_tf32(acc[0][j], af[0], bf);
                mma_tf32(acc[1][j], af[1], bf);
            }
        }
        // no trailing sync: stage st is next written by load(t+3) issued after
        // the barrier at iteration t+1, which all warps reach only after compute(t)
    }

    // =================== epilogues ===================
    if (MODE == 0) {
        if (blockIdx.x == 0) {
#pragma unroll
            for (int i = 0; i < 2; i++) {
                int rl = row0 + 32 * wm + 16 * i + g;
                int rh = rl + 8;
#pragma unroll
                for (int j = 0; j < 8; j++) {
                    int lc = 64 * wn + 8 * j + 2 * tg;
                    if (rl < M)
                        *reinterpret_cast<float2*>(&out[(size_t)rl * 128 + lc]) =
                            make_float2(acc[i][j][0], acc[i][j][1]);
                    if (rh < M)
                        *reinterpret_cast<float2*>(&out[(size_t)rh * 128 + lc]) =
                            make_float2(acc[i][j][2], acc[i][j][3]);
                }
            }
        } else {
            int coff = (blockIdx.x - 1) * 128;
#pragma unroll
            for (int i = 0; i < 2; i++) {
                int rl = row0 + 32 * wm + 16 * i + g;
                int rh = rl + 8;
#pragma unroll
                for (int j = 0; j < 8; j++) {
                    int lc = coff + 64 * wn + 8 * j + 2 * tg;
                    if (rl < M)
                        *reinterpret_cast<__half2*>(&outh[(size_t)rl * 256 + lc]) =
                            __floats2half2_rn(acc[i][j][0], acc[i][j][1]);
                    if (rh < M)
                        *reinterpret_cast<__half2*>(&outh[(size_t)rh * 256 + lc]) =
                            __floats2half2_rn(acc[i][j][2], acc[i][j][3]);
                }
            }
        }
    } else if (MODE == 1) {
#pragma unroll
        for (int i = 0; i < 2; i++) {
            int rl = row0 + 32 * wm + 16 * i + g;
            int rh = rl + 8;
#pragma unroll
            for (int j = 0; j < 8; j++) {
                int c = col0 + 64 * wn + 8 * j + 2 * tg;
                float2 bb = *reinterpret_cast<const float2*>(&bias[c]);
                float2 v0 = make_float2(fmaxf(acc[i][j][0] + bb.x, 0.f),
                                        fmaxf(acc[i][j][1] + bb.y, 0.f));
                float2 v1 = make_float2(fmaxf(acc[i][j][2] + bb.x, 0.f),
                                        fmaxf(acc[i][j][3] + bb.y, 0.f));
                if (rl < M) *reinterpret_cast<float2*>(&out[(size_t)rl * N + c]) = v0;
                if (rh < M) *reinterpret_cast<float2*>(&out[(size_t)rh * N + c]) = v1;
            }
        }
    } else {
        // MODE 2: bias + residual + LayerNorm (N == 128, grid.x == 1)
        float sl[2][2], s2l[2][2];
#pragma unroll
        for (int i = 0; i < 2; i++)
            for (int hf = 0; hf < 2; hf++) { sl[i][hf] = 0.f; s2l[i][hf] = 0.f; }

#pragma unroll
        for (int i = 0; i < 2; i++) {
            int rl = row0 + 32 * wm + 16 * i + g;
            int rh = rl + 8;
#pragma unroll
            for (int j = 0; j < 8; j++) {
                int c = 64 * wn + 8 * j + 2 * tg;
                float2 bb = *reinterpret_cast<const float2*>(&bias[c]);
                float2 r0 = make_float2(0.f, 0.f), r1 = make_float2(0.f, 0.f);
                if (rl < M) r0 = *reinterpret_cast<const float2*>(&res[(size_t)rl * 128 + c]);
                if (rh < M) r1 = *reinterpret_cast<const float2*>(&res[(size_t)rh * 128 + c]);
                acc[i][j][0] += bb.x + r0.x;
                acc[i][j][1] += bb.y + r0.y;
                acc[i][j][2] += bb.x + r1.x;
                acc[i][j][3] += bb.y + r1.y;
                sl[i][0]  += acc[i][j][0] + acc[i][j][1];
                s2l[i][0] += acc[i][j][0] * acc[i][j][0] + acc[i][j][1] * acc[i][j][1];
                sl[i][1]  += acc[i][j][2] + acc[i][j][3];
                s2l[i][1] += acc[i][j][2] * acc[i][j][2] + acc[i][j][3] * acc[i][j][3];
            }
        }
#pragma unroll
        for (int i = 0; i < 2; i++)
#pragma unroll
            for (int hf = 0; hf < 2; hf++) {
#pragma unroll
                for (int o = 1; o < 4; o <<= 1) {
                    sl[i][hf]  += __shfl_xor_sync(0xffffffffu, sl[i][hf],  o);
                    s2l[i][hf] += __shfl_xor_sync(0xffffffffu, s2l[i][hf], o);
                }
            }
        __syncthreads();
        float2* sbuf = reinterpret_cast<float2*>(&As[0][0]);
        if (tg == 0) {
#pragma unroll
            for (int i = 0; i < 2; i++) {
                int rloc = 32 * wm + 16 * i + g;
                sbuf[wn * 128 + rloc]     = make_float2(sl[i][0], s2l[i][0]);
                sbuf[wn * 128 + rloc + 8] = make_float2(sl[i][1], s2l[i][1]);
            }
        }
        __syncthreads();
        float mu[2][2], rstd[2][2];
#pragma unroll
        for (int i = 0; i < 2; i++)
#pragma unroll
            for (int hf = 0; hf < 2; hf++) {
                int rloc = 32 * wm + 16 * i + g + hf * 8;
                float2 p0 = sbuf[rloc];
                float2 p1 = sbuf[128 + rloc];
                float s  = p0.x + p1.x;
                float s2 = p0.y + p1.y;
                float m  = s * (1.f / 128.f);
                float var = s2 * (1.f / 128.f) - m * m;
                mu[i][hf]   = m;
                rstd[i][hf] = rsqrtf(var + 1e-5f);
            }
#pragma unroll
        for (int i = 0; i < 2; i++) {
            int rl = row0 + 32 * wm + 16 * i + g;
            int rh = rl + 8;
#pragma unroll
            for (int j = 0; j < 8; j++) {
                int c = 64 * wn + 8 * j + 2 * tg;
                float2 gg = *reinterpret_cast<const float2*>(&lng[c]);
                float2 bb = *reinterpret_cast<const float2*>(&lnb[c]);
                if (rl < M) {
                    float2 o0;
                    o0.x = (acc[i][j][0] - mu[i][0]) * rstd[i][0] * gg.x + bb.x;
                    o0.y = (acc[i][j][1] - mu[i][0]) * rstd[i][0] * gg.y + bb.y;
                    *reinterpret_cast<float2*>(&out[(size_t)rl * 128 + c]) = o0;
                }
                if (rh < M) {
                    float2 o1;
                    o1.x = (acc[i][j][2] - mu[i][1]) * rstd[i][1] * gg.x + bb.x;
                    o1.y = (acc[i][j][3] - mu[i][1]) * rstd[i][1] * gg.y + bb.y;
                    *reinterpret_cast<float2*>(&out[(size_t)rh * 128 + c]) = o1;
                }
            }
        }
    }
}

// ---------------- binning: count / scan / scatter -----------------------------
__global__ void __launch_bounds__(256)
count_kernel(const int* __restrict__ dst, int* __restrict__ cnt) {
    int e = blockIdx.x * blockDim.x + threadIdx.x;
    if (e < NE) atomicAdd(&cnt[dst[e]], 1);
}

__global__ void __launch_bounds__(1024)
scan_kernel(int* __restrict__ cnt, int* __restrict__ off, int* __restrict__ cur) {
    __shared__ int s[1024];
    const int t  = threadIdx.x;
    const int CH = (NN + 1023) / 1024;
    const int base = t * CH;
    int sum = 0;
    for (int i = 0; i < CH; i++) {
        int idx = base + i;
        if (idx < NN) sum += cnt[idx];
    }
    s[t] = sum;
    __syncthreads();
    for (int o = 1; o < 1024; o <<= 1) {
        int v = (t >= o) ? s[t - o] : 0;
        __syncthreads();
        s[t] += v;
        __syncthreads();
    }
    int run = (t == 0) ? 0 : s[t - 1];
    for (int i = 0; i < CH; i++) {
        int idx = base + i;
        if (idx < NN) {
            int c = cnt[idx];
            off[idx] = run; cur[idx] = run;
            run += c;
            cnt[idx] = 0;
        }
    }
    if (t == 1023) off[NN] = run;
}

__global__ void __launch_bounds__(256)
scatter_kernel(const int* __restrict__ src,
               const int* __restrict__ dst,
               int* __restrict__ cur,
               int* __restrict__ bin) {
    int e = blockIdx.x * blockDim.x + threadIdx.x;
    if (e >= NE) return;
    int pos = atomicAdd(&cur[dst[e]], 1);
    bin[pos] = src[e];
}

// ---------------- aggregation: 1 warp / node, fp16 KV, gather prefetch --------
__global__ void __launch_bounds__(256)
agg_kernel(const int* __restrict__ off,
           const int* __restrict__ bin,
           const float* __restrict__ Q,
           const __half* __restrict__ KV,
           float* __restrict__ head_out) {
    int n = (blockIdx.x * blockDim.x + threadIdx.x) >> 5;
    if (n >= NN) return;
    const int lane = threadIdx.x & 31;
    const int l16  = lane & 15;
    const int srcl = l16 & ~1;
    int beg = off[n], end = off[n + 1];

    float q[8];
    if (lane < 16) {
        float4 qa = *reinterpret_cast<const float4*>(&Q[(size_t)n * D + 8 * l16]);
        float4 qb = *reinterpret_cast<const float4*>(&Q[(size_t)n * D + 8 * l16 + 4]);
        q[0] = qa.x; q[1] = qa.y; q[2] = qa.z; q[3] = qa.w;
        q[4] = qb.x; q[5] = qb.y; q[6] = qb.z; q[7] = qb.w;
    }

    float acc[8];
#pragma unroll
    for (int j = 0; j < 8; j++) acc[j] = 0.f;
    float zt = 0.f;

    auto process = [&](const uint4& raw) {
        float2 a0 = __half22float2(*reinterpret_cast<const __half2*>(&raw.x));
        float2 a1 = __half22float2(*reinterpret_cast<const __half2*>(&raw.y));
        float2 a2 = __half22float2(*reinterpret_cast<const __half2*>(&raw.z));
        float2 a3 = __half22float2(*reinterpret_cast<const __half2*>(&raw.w));
        float p = a0.x * q[0] + a0.y * q[1] + a1.x * q[2] + a1.y * q[3]
                + a2.x * q[4] + a2.y * q[5] + a3.x * q[6] + a3.y * q[7];
        p += __shfl_xor_sync(0xffffffffu, p, 1);
        float sc = __expf(fminf(5.f, fmaxf(-5.f, p * 0.25f)));
        zt += sc;
        float sv = __shfl_sync(0xffffffffu, sc, srcl);
        if (lane >= 16) {
            acc[0] += a0.x * sv; acc[1] += a0.y * sv;
            acc[2] += a1.x * sv; acc[3] += a1.y * sv;
            acc[4] += a2.x * sv; acc[5] += a2.y * sv;
            acc[6] += a3.x * sv; acc[7] += a3.y * sv;
        }
    };

    if (beg < end) {
        int s0 = bin[beg];
        uint4 raw = *reinterpret_cast<const uint4*>(KV + (size_t)s0 * 256 + lane * 8);
        for (int i = beg; i + 1 < end; i++) {
            int sn = bin[i + 1];
            uint4 rawn = *reinterpret_cast<const uint4*>(KV + (size_t)sn * 256 + lane * 8);
            process(raw);
            raw = rawn;
        }
        process(raw);
    }

    float ztv = __shfl_sync(0xffffffffu, zt, srcl);
    if (lane >= 16) {
        if (ztv > 0.f) {
            float inv = 1.f / ztv;
#pragma unroll
            for (int j = 0; j < 8; j++) acc[j] *= inv;
        }
        float* op = head_out + (size_t)n * D + 8 * l16;
        *reinterpret_cast<float4*>(op)     = make_float4(acc[0], acc[1], acc[2], acc[3]);
        *reinterpret_cast<float4*>(op + 4) = make_float4(acc[4], acc[5], acc[6], acc[7]);
    }
}

// ---------------- launch -----------------------------------------------------
extern "C" void kernel_launch(void* const* d_in, const int* in_sizes, int n_in,
                              void* d_out, int out_size) {
    const float* h   = (const float*)d_in[0];
    const int*   src = (const int*)  d_in[1];
    const int*   dst = (const int*)  d_in[2];
    const float* Wq  = (const float*)d_in[3];
    const float* Wk  = (const float*)d_in[4];
    const float* Wv  = (const float*)d_in[5];
    const float* Wo  = (const float*)d_in[6];
    const float* bo  = (const float*)d_in[7];
    const float* g1  = (const float*)d_in[8];
    const float* b1  = (const float*)d_in[9];
    const float* g2  = (const float*)d_in[10];
    const float* b2  = (const float*)d_in[11];
    const float* W1  = (const float*)d_in[12];
    const float* c1  = (const float*)d_in[13];
    const float* W2  = (const float*)d_in[14];
    const float* c2  = (const float*)d_in[15];
    float* out = (float*)d_out;

    float *Qp, *Wpkp, *wVp, *hhp, *tp;
    __half* KVp;
    int *cntp, *offp, *curp, *binp;
    cudaGetSymbolAddress((void**)&Qp,   g_Q);
    cudaGetSymbolAddress((void**)&KVp,  g_KVh);
    cudaGetSymbolAddress((void**)&Wpkp, g_Wpk);
    cudaGetSymbolAddress((void**)&wVp,  g_wV);
    cudaGetSymbolAddress((void**)&hhp,  g_hh);
    cudaGetSymbolAddress((void**)&tp,   g_t);
    cudaGetSymbolAddress((void**)&cntp, g_cnt);
    cudaGetSymbolAddress((void**)&offp, g_off);
    cudaGetSymbolAddress((void**)&curp, g_cur);
    cudaGetSymbolAddress((void**)&binp, g_bin);

    const int GY = (NN + 127) / 128;   // 782

    // Launch order chosen so ncu (-s 5 -c 1) profiles agg_kernel (launch #6).
    // 1: packW (independent of everything)
    packW_kernel<<<(D * D + 255) / 256, 256>>>(Wq, Wk, Wv, Wpkp);

    // 2-4: binning by dst (cnt self-zeroing in scan)
    count_kernel<<<(NE + 255) / 256, 256>>>(dst, cntp);
    scan_kernel<<<1, 1024>>>(cntp, offp, curp);
    scatter_kernel<<<(NE + 255) / 256, 256>>>(src, dst, curp, binp);

    // 5: fused QKV GEMM (tf32, 3-stage cp.async), Q fp32 + KV fp16 outputs
    mma_gemm<0><<<dim3(3, GY), 256>>>(h, Wpkp, nullptr, nullptr, nullptr, nullptr,
                                      Qp, KVp, NN, 3 * D, D);

    // 6: attention aggregation (atomic-free, fp16 gathers, pipelined)
    {
        int blocks = (NN * 32 + 255) / 256;
        agg_kernel<<<blocks, 256>>>(offp, binp, Qp, KVp, wVp);
    }

    // 7: hh = LN(h + head_out @ Wo + bo)
    mma_gemm<2><<<dim3(1, GY), 256>>>(wVp, Wo, bo, h, g1, b1,
                                      hhp, nullptr, NN, D, D);

    // 8: t = relu(hh @ W1 + c1)
    mma_gemm<1><<<dim3(2, GY), 256>>>(hhp, W1, c1, nullptr, nullptr, nullptr,
                                      tp, nullptr, NN, 2 * D, D);

    // 9: out = LN(hh + t @ W2 + c2)
    mma_gemm<2><<<dim3(1, GY), 256>>>(tp, W2, c2, hhp, g2, b2,
                                      out, nullptr, NN, D, 2 * D);
}

// round 15
// speedup vs baseline: 1.2261x; 1.0064x over previous
#include <cuda_runtime.h>
#include <cuda_fp16.h>
#include <cstdint>

constexpr int NN = 100000;   // nodes
constexpr int NE = 1600000;  // edges
constexpr int D  = 128;
// H=8, DH=16, scale=0.25

// ---------------- scratch ----------------------------------------------------
__device__ float  g_Q  [NN * D];        // Q rows fp32 (streamed in agg)
__device__ __half g_KVh[NN * 2 * D];    // per node: [K(128) | V(128)] fp16 (gathered)
__device__ float  g_Wpk[D * 3 * D];     // packed weights [k][Wq|Wk|Wv]
__device__ float  g_wV [NN * D];        // head_out
__device__ float  g_hh [NN * D];
__device__ float  g_t  [NN * 2 * D];    // FFN intermediate fp32
__device__ int    g_cnt[NN];            // zero-init; scan re-zeroes each pass
__device__ int    g_off[NN + 1];
__device__ int    g_cur[NN];
__device__ int    g_bin[NE];            // src ids binned by dst

// ---------------- helpers -----------------------------------------------------
__device__ __forceinline__ void mma_tf32(float* d, const uint32_t* a, const uint32_t* b) {
    asm volatile(
        "mma.sync.aligned.m16n8k8.row.col.f32.tf32.tf32.f32 "
        "{%0,%1,%2,%3}, {%4,%5,%6,%7}, {%8,%9}, {%0,%1,%2,%3};"
        : "+f"(d[0]), "+f"(d[1]), "+f"(d[2]), "+f"(d[3])
        : "r"(a[0]), "r"(a[1]), "r"(a[2]), "r"(a[3]), "r"(b[0]), "r"(b[1]));
}

__device__ __forceinline__ void cpa16(uint32_t dst, const void* src, int sz) {
    asm volatile("cp.async.ca.shared.global [%0], [%1], 16, %2;"
                 :: "r"(dst), "l"(src), "r"(sz));
}
__device__ __forceinline__ void cpa_commit() {
    asm volatile("cp.async.commit_group;");
}
template <int N_>
__device__ __forceinline__ void cpa_wait() {
    asm volatile("cp.async.wait_group %0;" :: "n"(N_));
}

// ---------------- pack Wq|Wk|Wv into [128 x 384] -----------------------------
__global__ void __launch_bounds__(256)
packW_kernel(const float* __restrict__ Wq,
             const float* __restrict__ Wk,
             const float* __restrict__ Wv,
             float* __restrict__ P) {
    int i = blockIdx.x * blockDim.x + threadIdx.x;
    if (i >= D * D) return;
    int k = i / D, c = i % D;
    P[(size_t)k * (3 * D) + c]         = Wq[i];
    P[(size_t)k * (3 * D) + D + c]     = Wk[i];
    P[(size_t)k * (3 * D) + 2 * D + c] = Wv[i];
}

// ====== tf32 tensor-core GEMM, BM=BN=128, BK=16, cp.async 3-stage pipeline ====
// MODE 0: QKV split store (out=Q fp32 stride 128; outh=KV fp16 stride 256)
// MODE 1: out = relu(A@B + bias), fp32, generic N (grid.x = N/128)
// MODE 2: out = LN(res + A@B + bias)*lng + lnb, N==128, grid.x==1
template <int MODE>
__global__ void __launch_bounds__(256, 2)
mma_gemm(const float* __restrict__ A, const float* __restrict__ B,
         const float* __restrict__ bias, const float* __restrict__ res,
         const float* __restrict__ lng, const float* __restrict__ lnb,
         float* __restrict__ out, __half* __restrict__ outh,
         int M, int N, int K) {
    constexpr int SA = 20;
    constexpr int SB = 136;
    constexpr int ST = 3;
    __shared__ __align__(16) float As[ST][128 * SA];
    __shared__ __align__(16) float Bs[ST][16 * SB];

    const int tid  = threadIdx.x;
    const int warp = tid >> 5;
    const int lane = tid & 31;
    const int g    = lane >> 2;
    const int tg   = lane & 3;
    const int wm   = warp & 3;
    const int wn   = warp >> 2;
    const int row0 = blockIdx.y * 128;
    const int col0 = blockIdx.x * 128;

    float acc[2][8][4];
#pragma unroll
    for (int i = 0; i < 2; i++)
#pragma unroll
        for (int j = 0; j < 8; j++)
#pragma unroll
            for (int q = 0; q < 4; q++) acc[i][j][q] = 0.f;

    auto load_tile = [&](int kt, int st) {
        const int k0 = kt * 16;
#pragma unroll
        for (int l = 0; l < 2; l++) {
            int c  = tid + 256 * l;
            int m  = c >> 2;
            int kc = (c & 3) * 4;
            const float* srcA = A + (size_t)(row0 + m) * K + k0 + kc;
            int sz = (row0 + m < M) ? 16 : 0;
            uint32_t dstA = (uint32_t)__cvta_generic_to_shared(&As[st][m * SA + kc]);
            cpa16(dstA, srcA, sz);
        }
#pragma unroll
        for (int l = 0; l < 2; l++) {
            int c  = tid + 256 * l;
            int kr = c >> 5;
            int nc = (c & 31) * 4;
            const float* srcB = B + (size_t)(k0 + kr) * N + col0 + nc;
            uint32_t dstB = (uint32_t)__cvta_generic_to_shared(&Bs[st][kr * SB + nc]);
            cpa16(dstB, srcB, 16);
        }
    };

    const int T = K / 16;
    load_tile(0, 0);
    cpa_commit();
    if (T > 1) { load_tile(1, 1); cpa_commit(); }

    for (int t = 0; t < T; t++) {
        const int st = t % ST;
        if (t + 1 < T) cpa_wait<1>();
        else           cpa_wait<0>();
        __syncthreads();
        if (t + 2 < T) {
            load_tile(t + 2, (t + 2) % ST);
            cpa_commit();
        }

#pragma unroll
        for (int ks = 0; ks < 2; ks++) {
            const int kk = ks * 8;
            uint32_t af[2][4];
#pragma unroll
            for (int i = 0; i < 2; i++) {
                int rb = 32 * wm + 16 * i + g;
                af[i][0] = __float_as_uint(As[st][rb * SA + kk + tg]);
                af[i][1] = __float_as_uint(As[st][(rb + 8) * SA + kk + tg]);
                af[i][2] = __float_as_uint(As[st][rb * SA + kk + tg + 4]);
                af[i][3] = __float_as_uint(As[st][(rb + 8) * SA + kk + tg + 4]);
            }
#pragma unroll
            for (int j = 0; j < 8; j++) {
                int nb = 64 * wn + 8 * j + g;
                uint32_t bf[2];
                bf[0] = __float_as_uint(Bs[st][(kk + tg) * SB + nb]);
                bf[1] = __float_as_uint(Bs[st][(kk + tg + 4) * SB + nb]);
                mma_tf32(acc[0][j], af[0], bf);
                mma_tf32(acc[1][j], af[1], bf);
            }
        }
    }

    // =================== epilogues ===================
    if (MODE == 0) {
        if (blockIdx.x == 0) {
#pragma unroll
            for (int i = 0; i < 2; i++) {
                int rl = row0 + 32 * wm + 16 * i + g;
                int rh = rl + 8;
#pragma unroll
                for (int j = 0; j < 8; j++) {
                    int lc = 64 * wn + 8 * j + 2 * tg;
                    if (rl < M)
                        *reinterpret_cast<float2*>(&out[(size_t)rl * 128 + lc]) =
                            make_float2(acc[i][j][0], acc[i][j][1]);
                    if (rh < M)
                        *reinterpret_cast<float2*>(&out[(size_t)rh * 128 + lc]) =
                            make_float2(acc[i][j][2], acc[i][j][3]);
                }
            }
        } else {
            int coff = (blockIdx.x - 1) * 128;
#pragma unroll
            for (int i = 0; i < 2; i++) {
                int rl = row0 + 32 * wm + 16 * i + g;
                int rh = rl + 8;
#pragma unroll
                for (int j = 0; j < 8; j++) {
                    int lc = coff + 64 * wn + 8 * j + 2 * tg;
                    if (rl < M)
                        *reinterpret_cast<__half2*>(&outh[(size_t)rl * 256 + lc]) =
                            __floats2half2_rn(acc[i][j][0], acc[i][j][1]);
                    if (rh < M)
                        *reinterpret_cast<__half2*>(&outh[(size_t)rh * 256 + lc]) =
                            __floats2half2_rn(acc[i][j][2], acc[i][j][3]);
                }
            }
        }
    } else if (MODE == 1) {
#pragma unroll
        for (int i = 0; i < 2; i++) {
            int rl = row0 + 32 * wm + 16 * i + g;
            int rh = rl + 8;
#pragma unroll
            for (int j = 0; j < 8; j++) {
                int c = col0 + 64 * wn + 8 * j + 2 * tg;
                float2 bb = *reinterpret_cast<const float2*>(&bias[c]);
                float2 v0 = make_float2(fmaxf(acc[i][j][0] + bb.x, 0.f),
                                        fmaxf(acc[i][j][1] + bb.y, 0.f));
                float2 v1 = make_float2(fmaxf(acc[i][j][2] + bb.x, 0.f),
                                        fmaxf(acc[i][j][3] + bb.y, 0.f));
                if (rl < M) *reinterpret_cast<float2*>(&out[(size_t)rl * N + c]) = v0;
                if (rh < M) *reinterpret_cast<float2*>(&out[(size_t)rh * N + c]) = v1;
            }
        }
    } else {
        float sl[2][2], s2l[2][2];
#pragma unroll
        for (int i = 0; i < 2; i++)
            for (int hf = 0; hf < 2; hf++) { sl[i][hf] = 0.f; s2l[i][hf] = 0.f; }

#pragma unroll
        for (int i = 0; i < 2; i++) {
            int rl = row0 + 32 * wm + 16 * i + g;
            int rh = rl + 8;
#pragma unroll
            for (int j = 0; j < 8; j++) {
                int c = 64 * wn + 8 * j + 2 * tg;
                float2 bb = *reinterpret_cast<const float2*>(&bias[c]);
                float2 r0 = make_float2(0.f, 0.f), r1 = make_float2(0.f, 0.f);
                if (rl < M) r0 = *reinterpret_cast<const float2*>(&res[(size_t)rl * 128 + c]);
                if (rh < M) r1 = *reinterpret_cast<const float2*>(&res[(size_t)rh * 128 + c]);
                acc[i][j][0] += bb.x + r0.x;
                acc[i][j][1] += bb.y + r0.y;
                acc[i][j][2] += bb.x + r1.x;
                acc[i][j][3] += bb.y + r1.y;
                sl[i][0]  += acc[i][j][0] + acc[i][j][1];
                s2l[i][0] += acc[i][j][0] * acc[i][j][0] + acc[i][j][1] * acc[i][j][1];
                sl[i][1]  += acc[i][j][2] + acc[i][j][3];
                s2l[i][1] += acc[i][j][2] * acc[i][j][2] + acc[i][j][3] * acc[i][j][3];
            }
        }
#pragma unroll
        for (int i = 0; i < 2; i++)
#pragma unroll
            for (int hf = 0; hf < 2; hf++) {
#pragma unroll
                for (int o = 1; o < 4; o <<= 1) {
                    sl[i][hf]  += __shfl_xor_sync(0xffffffffu, sl[i][hf],  o);
                    s2l[i][hf] += __shfl_xor_sync(0xffffffffu, s2l[i][hf], o);
                }
            }
        __syncthreads();
        float2* sbuf = reinterpret_cast<float2*>(&As[0][0]);
        if (tg == 0) {
#pragma unroll
            for (int i = 0; i < 2; i++) {
                int rloc = 32 * wm + 16 * i + g;
                sbuf[wn * 128 + rloc]     = make_float2(sl[i][0], s2l[i][0]);
                sbuf[wn * 128 + rloc + 8] = make_float2(sl[i][1], s2l[i][1]);
            }
        }
        __syncthreads();
        float mu[2][2], rstd[2][2];
#pragma unroll
        for (int i = 0; i < 2; i++)
#pragma unroll
            for (int hf = 0; hf < 2; hf++) {
                int rloc = 32 * wm + 16 * i + g + hf * 8;
                float2 p0 = sbuf[rloc];
                float2 p1 = sbuf[128 + rloc];
                float s  = p0.x + p1.x;
                float s2 = p0.y + p1.y;
                float m  = s * (1.f / 128.f);
                float var = s2 * (1.f / 128.f) - m * m;
                mu[i][hf]   = m;
                rstd[i][hf] = rsqrtf(var + 1e-5f);
            }
#pragma unroll
        for (int i = 0; i < 2; i++) {
            int rl = row0 + 32 * wm + 16 * i + g;
            int rh = rl + 8;
#pragma unroll
            for (int j = 0; j < 8; j++) {
                int c = 64 * wn + 8 * j + 2 * tg;
                float2 gg = *reinterpret_cast<const float2*>(&lng[c]);
                float2 bb = *reinterpret_cast<const float2*>(&lnb[c]);
                if (rl < M) {
                    float2 o0;
                    o0.x = (acc[i][j][0] - mu[i][0]) * rstd[i][0] * gg.x + bb.x;
                    o0.y = (acc[i][j][1] - mu[i][0]) * rstd[i][0] * gg.y + bb.y;
                    *reinterpret_cast<float2*>(&out[(size_t)rl * 128 + c]) = o0;
                }
                if (rh < M) {
                    float2 o1;
                    o1.x = (acc[i][j][2] - mu[i][1]) * rstd[i][1] * gg.x + bb.x;
                    o1.y = (acc[i][j][3] - mu[i][1]) * rstd[i][1] * gg.y + bb.y;
                    *reinterpret_cast<float2*>(&out[(size_t)rh * 128 + c]) = o1;
                }
            }
        }
    }
}

// ---------------- binning: count / scan / scatter -----------------------------
__global__ void __launch_bounds__(256)
count_kernel(const int* __restrict__ dst, int* __restrict__ cnt) {
    int e = blockIdx.x * blockDim.x + threadIdx.x;
    if (e < NE) atomicAdd(&cnt[dst[e]], 1);
}

__global__ void __launch_bounds__(1024)
scan_kernel(int* __restrict__ cnt, int* __restrict__ off, int* __restrict__ cur) {
    __shared__ int s[1024];
    const int t  = threadIdx.x;
    const int CH = (NN + 1023) / 1024;
    const int base = t * CH;
    int sum = 0;
    for (int i = 0; i < CH; i++) {
        int idx = base + i;
        if (idx < NN) sum += cnt[idx];
    }
    s[t] = sum;
    __syncthreads();
    for (int o = 1; o < 1024; o <<= 1) {
        int v = (t >= o) ? s[t - o] : 0;
        __syncthreads();
        s[t] += v;
        __syncthreads();
    }
    int run = (t == 0) ? 0 : s[t - 1];
    for (int i = 0; i < CH; i++) {
        int idx = base + i;
        if (idx < NN) {
            int c = cnt[idx];
            off[idx] = run; cur[idx] = run;
            run += c;
            cnt[idx] = 0;
        }
    }
    if (t == 1023) off[NN] = run;
}

__global__ void __launch_bounds__(256)
scatter_kernel(const int* __restrict__ src,
               const int* __restrict__ dst,
               int* __restrict__ cur,
               int* __restrict__ bin) {
    int e = blockIdx.x * blockDim.x + threadIdx.x;
    if (e >= NE) return;
    int pos = atomicAdd(&cur[dst[e]], 1);
    bin[pos] = src[e];
}

// ---------------- aggregation: 1 warp / node, fp16 KV, gather prefetch --------
// Streaming accesses (Q, bin, head_out) use evict-first cache policy so the
// gathered KV table (51 MB) stays L2-resident.
__global__ void __launch_bounds__(256)
agg_kernel(const int* __restrict__ off,
           const int* __restrict__ bin,
           const float* __restrict__ Q,
           const __half* __restrict__ KV,
           float* __restrict__ head_out) {
    int n = (blockIdx.x * blockDim.x + threadIdx.x) >> 5;
    if (n >= NN) return;
    const int lane = threadIdx.x & 31;
    const int l16  = lane & 15;
    const int srcl = l16 & ~1;
    int beg = off[n], end = off[n + 1];

    float q[8];
    if (lane < 16) {
        float4 qa = __ldcs(reinterpret_cast<const float4*>(&Q[(size_t)n * D + 8 * l16]));
        float4 qb = __ldcs(reinterpret_cast<const float4*>(&Q[(size_t)n * D + 8 * l16 + 4]));
        q[0] = qa.x; q[1] = qa.y; q[2] = qa.z; q[3] = qa.w;
        q[4] = qb.x; q[5] = qb.y; q[6] = qb.z; q[7] = qb.w;
    }

    float acc[8];
#pragma unroll
    for (int j = 0; j < 8; j++) acc[j] = 0.f;
    float zt = 0.f;

    auto process = [&](const uint4& raw) {
        float2 a0 = __half22float2(*reinterpret_cast<const __half2*>(&raw.x));
        float2 a1 = __half22float2(*reinterpret_cast<const __half2*>(&raw.y));
        float2 a2 = __half22float2(*reinterpret_cast<const __half2*>(&raw.z));
        float2 a3 = __half22float2(*reinterpret_cast<const __half2*>(&raw.w));
        float p = a0.x * q[0] + a0.y * q[1] + a1.x * q[2] + a1.y * q[3]
                + a2.x * q[4] + a2.y * q[5] + a3.x * q[6] + a3.y * q[7];
        p += __shfl_xor_sync(0xffffffffu, p, 1);
        float sc = __expf(fminf(5.f, fmaxf(-5.f, p * 0.25f)));
        zt += sc;
        float sv = __shfl_sync(0xffffffffu, sc, srcl);
        if (lane >= 16) {
            acc[0] += a0.x * sv; acc[1] += a0.y * sv;
            acc[2] += a1.x * sv; acc[3] += a1.y * sv;
            acc[4] += a2.x * sv; acc[5] += a2.y * sv;
            acc[6] += a3.x * sv; acc[7] += a3.y * sv;
        }
    };

    if (beg < end) {
        int s0 = __ldcs(&bin[beg]);
        uint4 raw = *reinterpret_cast<const uint4*>(KV + (size_t)s0 * 256 + lane * 8);
        for (int i = beg; i + 1 < end; i++) {
            int sn = __ldcs(&bin[i + 1]);
            uint4 rawn = *reinterpret_cast<const uint4*>(KV + (size_t)sn * 256 + lane * 8);
            process(raw);
            raw = rawn;
        }
        process(raw);
    }

    float ztv = __shfl_sync(0xffffffffu, zt, srcl);
    if (lane >= 16) {
        if (ztv > 0.f) {
            float inv = 1.f / ztv;
#pragma unroll
            for (int j = 0; j < 8; j++) acc[j] *= inv;
        }
        float* op = head_out + (size_t)n * D + 8 * l16;
        __stcs(reinterpret_cast<float4*>(op),     make_float4(acc[0], acc[1], acc[2], acc[3]));
        __stcs(reinterpret_cast<float4*>(op + 4), make_float4(acc[4], acc[5], acc[6], acc[7]));
    }
}

// ---------------- launch -----------------------------------------------------
extern "C" void kernel_launch(void* const* d_in, const int* in_sizes, int n_in,
                              void* d_out, int out_size) {
    const float* h   = (const float*)d_in[0];
    const int*   src = (const int*)  d_in[1];
    const int*   dst = (const int*)  d_in[2];
    const float* Wq  = (const float*)d_in[3];
    const float* Wk  = (const float*)d_in[4];
    const float* Wv  = (const float*)d_in[5];
    const float* Wo  = (const float*)d_in[6];
    const float* bo  = (const float*)d_in[7];
    const float* g1  = (const float*)d_in[8];
    const float* b1  = (const float*)d_in[9];
    const float* g2  = (const float*)d_in[10];
    const float* b2  = (const float*)d_in[11];
    const float* W1  = (const float*)d_in[12];
    const float* c1  = (const float*)d_in[13];
    const float* W2  = (const float*)d_in[14];
    const float* c2  = (const float*)d_in[15];
    float* out = (float*)d_out;

    float *Qp, *Wpkp, *wVp, *hhp, *tp;
    __half* KVp;
    int *cntp, *offp, *curp, *binp;
    cudaGetSymbolAddress((void**)&Qp,   g_Q);
    cudaGetSymbolAddress((void**)&KVp,  g_KVh);
    cudaGetSymbolAddress((void**)&Wpkp, g_Wpk);
    cudaGetSymbolAddress((void**)&wVp,  g_wV);
    cudaGetSymbolAddress((void**)&hhp,  g_hh);
    cudaGetSymbolAddress((void**)&tp,   g_t);
    cudaGetSymbolAddress((void**)&cntp, g_cnt);
    cudaGetSymbolAddress((void**)&offp, g_off);
    cudaGetSymbolAddress((void**)&curp, g_cur);
    cudaGetSymbolAddress((void**)&binp, g_bin);

    const int GY = (NN + 127) / 128;   // 782

    // Launch order: #4 = QKV GEMM (ncu captures launch #4).
    // 1: packW
    packW_kernel<<<(D * D + 255) / 256, 256>>>(Wq, Wk, Wv, Wpkp);
    // 2-3: count + scan
    count_kernel<<<(NE + 255) / 256, 256>>>(dst, cntp);
    scan_kernel<<<1, 1024>>>(cntp, offp, curp);
    // 4: fused QKV GEMM (profiled)
    mma_gemm<0><<<dim3(3, GY), 256>>>(h, Wpkp, nullptr, nullptr, nullptr, nullptr,
                                      Qp, KVp, NN, 3 * D, D);
    // 5: scatter (needs scan only)
    scatter_kernel<<<(NE + 255) / 256, 256>>>(src, dst, curp, binp);
    // 6: attention aggregation
    {
        int blocks = (NN * 32 + 255) / 256;
        agg_kernel<<<blocks, 256>>>(offp, binp, Qp, KVp, wVp);
    }
    // 7: hh = LN(h + head_out @ Wo + bo)
    mma_gemm<2><<<dim3(1, GY), 256>>>(wVp, Wo, bo, h, g1, b1,
                                      hhp, nullptr, NN, D, D);
    // 8: t = relu(hh @ W1 + c1)
    mma_gemm<1><<<dim3(2, GY), 256>>>(hhp, W1, c1, nullptr, nullptr, nullptr,
                                      tp, nullptr, NN, 2 * D, D);
    // 9: out = LN(hh + t @ W2 + c2)
    mma_gemm<2><<<dim3(1, GY), 256>>>(tp, W2, c2, hhp, g2, b2,
                                      out, nullptr, NN, D, 2 * D);
}